// round 1
// baseline (speedup 1.0000x reference)
#include <cuda_runtime.h>
#include <math.h>

// Problem constants
#define BB 32
#define JJ 512
#define EE 512
#define HH 8
#define HDQ 64
#define MROWS (BB*JJ)          // 16384
#define EPSF 1e-7f

// Scratch (device globals; no allocation allowed)
__device__ float g_qkv[MROWS * 3 * EE];   // [16384,1536]  q|k|v per row
__device__ float g_ztan[MROWS * EE];      // attn @ v, (B,J,E)
__device__ float g_ztan2[MROWS * EE];     // after out-proj

// ---------------------------------------------------------------------------
// log_map0_spatial: per row of x (513 wide) -> x_tan (512 wide)
// ---------------------------------------------------------------------------
__global__ void xtan_kernel(const float* __restrict__ x, float* __restrict__ xt) {
    int row = blockIdx.x;
    const float* p = x + (size_t)row * 513;
    float* o = xt + (size_t)row * 512;
    int t = threadIdx.x;  // 128 threads
    float v[4];
    float s = 0.f;
#pragma unroll
    for (int q = 0; q < 4; q++) { v[q] = p[1 + t + q * 128]; s += v[q] * v[q]; }
#pragma unroll
    for (int o2 = 16; o2 > 0; o2 >>= 1) s += __shfl_xor_sync(0xffffffffu, s, o2);
    __shared__ float sb[4];
    if ((t & 31) == 0) sb[t >> 5] = s;
    __syncthreads();
    float tot = sb[0] + sb[1] + sb[2] + sb[3];
    float nrm = sqrtf(tot);
    float x0 = fmaxf(p[0], 1.0f + 1e-7f);
    float theta = acoshf(x0);
    float sc = theta / fmaxf(nrm, EPSF);
#pragma unroll
    for (int q = 0; q < 4; q++) o[t + q * 128] = sc * v[q];
}

// ---------------------------------------------------------------------------
// exp_map0: per row of z_tan (512 wide) -> z_manifold (513 wide)
// ---------------------------------------------------------------------------
__global__ void expmap_kernel(const float* __restrict__ zt, float* __restrict__ zm) {
    int row = blockIdx.x;
    const float* p = zt + (size_t)row * 512;
    float* o = zm + (size_t)row * 513;
    int t = threadIdx.x;
    float v[4];
    float s = 0.f;
#pragma unroll
    for (int q = 0; q < 4; q++) { v[q] = p[t + q * 128]; s += v[q] * v[q]; }
#pragma unroll
    for (int o2 = 16; o2 > 0; o2 >>= 1) s += __shfl_xor_sync(0xffffffffu, s, o2);
    __shared__ float sb[4];
    if ((t & 31) == 0) sb[t >> 5] = s;
    __syncthreads();
    float tot = sb[0] + sb[1] + sb[2] + sb[3];
    float nrm = sqrtf(tot);
    float sc = sinhf(nrm) / fmaxf(nrm, EPSF);
    if (t == 0) o[0] = coshf(nrm);
#pragma unroll
    for (int q = 0; q < 4; q++) o[1 + t + q * 128] = sc * v[q];
}

// ---------------------------------------------------------------------------
// Generic NT GEMM: C[M,N] (+)= A[M,K] * W[N,K]^T  (+bias)
// BM=BN=128, BK=8, 256 threads, 8x8 per thread. Grid must cover exactly.
// ---------------------------------------------------------------------------
__global__ void gemm_nt(const float* __restrict__ A, int lda,
                        const float* __restrict__ W, int ldb,
                        float* __restrict__ C, int ldc,
                        int K, const float* __restrict__ bias, int accflag) {
    __shared__ float As[8][128];
    __shared__ float Bs[8][128];
    int tid = threadIdx.x;
    int tx = tid & 15, ty = tid >> 4;
    const float* Ab = A + (size_t)blockIdx.y * 128 * lda;
    const float* Bw = W + (size_t)blockIdx.x * 128 * ldb;
    float acc[8][8];
#pragma unroll
    for (int i = 0; i < 8; i++)
#pragma unroll
        for (int j = 0; j < 8; j++) acc[i][j] = 0.f;

    for (int k0 = 0; k0 < K; k0 += 8) {
#pragma unroll
        for (int q = 0; q < 4; q++) {
            int i = tid + q * 256;
            int r = i >> 3, c = i & 7;
            As[c][r] = Ab[(size_t)r * lda + k0 + c];
            Bs[c][r] = Bw[(size_t)r * ldb + k0 + c];
        }
        __syncthreads();
#pragma unroll
        for (int kk = 0; kk < 8; kk++) {
            float4 a0 = *reinterpret_cast<const float4*>(&As[kk][ty * 8]);
            float4 a1 = *reinterpret_cast<const float4*>(&As[kk][ty * 8 + 4]);
            float4 b0 = *reinterpret_cast<const float4*>(&Bs[kk][tx * 8]);
            float4 b1 = *reinterpret_cast<const float4*>(&Bs[kk][tx * 8 + 4]);
            float a[8] = {a0.x, a0.y, a0.z, a0.w, a1.x, a1.y, a1.z, a1.w};
            float b[8] = {b0.x, b0.y, b0.z, b0.w, b1.x, b1.y, b1.z, b1.w};
#pragma unroll
            for (int i = 0; i < 8; i++)
#pragma unroll
                for (int j = 0; j < 8; j++) acc[i][j] += a[i] * b[j];
        }
        __syncthreads();
    }
    int row0 = blockIdx.y * 128 + ty * 8;
    int col0 = blockIdx.x * 128 + tx * 8;
#pragma unroll
    for (int i = 0; i < 8; i++)
#pragma unroll
        for (int j = 0; j < 8; j++) {
            size_t idx = (size_t)(row0 + i) * ldc + col0 + j;
            float v = acc[i][j];
            if (bias) v += bias[col0 + j];
            if (accflag) v += C[idx];
            C[idx] = v;
        }
}

// ---------------------------------------------------------------------------
// S = Q K^T * scale + topo_bias, per head; writes attn output region (pre-softmax)
// grid: (J/64, J/64, B*H), 256 threads, 4x4 per thread, K=64
// ---------------------------------------------------------------------------
__global__ void s_kernel(const float* __restrict__ qkv, const float* __restrict__ topo,
                         float* __restrict__ attn) {
    int head = blockIdx.z;
    int b = head >> 3, h = head & 7;
    int k0 = blockIdx.x * 64, q0 = blockIdx.y * 64;
    __shared__ float Qs[64][65];
    __shared__ float Ks[64][65];
    int tid = threadIdx.x;
    const float* qbase = qkv + (size_t)b * 512 * 1536 + h * 64;
#pragma unroll
    for (int q = 0; q < 16; q++) {
        int i = tid + q * 256;
        int r = i >> 6, c = i & 63;
        Qs[r][c] = qbase[(size_t)(q0 + r) * 1536 + c];
        Ks[r][c] = qbase[(size_t)(k0 + r) * 1536 + 512 + c];
    }
    __syncthreads();
    int tx = tid & 15, ty = tid >> 4;
    float acc[4][4];
#pragma unroll
    for (int i = 0; i < 4; i++)
#pragma unroll
        for (int j = 0; j < 4; j++) acc[i][j] = 0.f;
#pragma unroll 8
    for (int kk = 0; kk < 64; kk++) {
        float a[4], bv[4];
#pragma unroll
        for (int i = 0; i < 4; i++) a[i] = Qs[ty * 4 + i][kk];
#pragma unroll
        for (int j = 0; j < 4; j++) bv[j] = Ks[tx * 4 + j][kk];
#pragma unroll
        for (int i = 0; i < 4; i++)
#pragma unroll
            for (int j = 0; j < 4; j++) acc[i][j] += a[i] * bv[j];
    }
    const float scale = 0.125f;  // 64^-0.5
#pragma unroll
    for (int i = 0; i < 4; i++)
#pragma unroll
        for (int j = 0; j < 4; j++) {
            int qi = q0 + ty * 4 + i, kj = k0 + tx * 4 + j;
            attn[((size_t)head * 512 + qi) * 512 + kj] =
                acc[i][j] * scale + topo[(size_t)qi * 512 + kj];
        }
}

// ---------------------------------------------------------------------------
// Row softmax in place over attn: one block per row (512 cols), 128 threads
// ---------------------------------------------------------------------------
__global__ void softmax_kernel(float* __restrict__ attn) {
    size_t row = blockIdx.x;
    float* p = attn + row * 512;
    int t = threadIdx.x;
    float4 v = reinterpret_cast<float4*>(p)[t];
    float m = fmaxf(fmaxf(v.x, v.y), fmaxf(v.z, v.w));
#pragma unroll
    for (int o = 16; o > 0; o >>= 1) m = fmaxf(m, __shfl_xor_sync(0xffffffffu, m, o));
    __shared__ float sb[4];
    if ((t & 31) == 0) sb[t >> 5] = m;
    __syncthreads();
    m = fmaxf(fmaxf(sb[0], sb[1]), fmaxf(sb[2], sb[3]));
    __syncthreads();
    v.x = expf(v.x - m); v.y = expf(v.y - m); v.z = expf(v.z - m); v.w = expf(v.w - m);
    float s = v.x + v.y + v.z + v.w;
#pragma unroll
    for (int o = 16; o > 0; o >>= 1) s += __shfl_xor_sync(0xffffffffu, s, o);
    if ((t & 31) == 0) sb[t >> 5] = s;
    __syncthreads();
    s = sb[0] + sb[1] + sb[2] + sb[3];
    float inv = 1.0f / s;
    v.x *= inv; v.y *= inv; v.z *= inv; v.w *= inv;
    reinterpret_cast<float4*>(p)[t] = v;
}

// ---------------------------------------------------------------------------
// z = attn @ V per head, writes (B,J,E) layout. grid (1, J/64, B*H)
// BM=64, BN=64, BK=32, 256 threads, 4x4 per thread
// ---------------------------------------------------------------------------
__global__ void pv_kernel(const float* __restrict__ attn, const float* __restrict__ qkv,
                          float* __restrict__ ztan) {
    int head = blockIdx.z;
    int b = head >> 3, h = head & 7;
    int q0 = blockIdx.y * 64;
    __shared__ float Ps[64][33];
    __shared__ float Vs[32][65];
    const float* arow = attn + ((size_t)head * 512 + q0) * 512;
    const float* vbase = qkv + (size_t)b * 512 * 1536 + 1024 + h * 64;
    int tid = threadIdx.x;
    int tx = tid & 15, ty = tid >> 4;
    float acc[4][4];
#pragma unroll
    for (int i = 0; i < 4; i++)
#pragma unroll
        for (int j = 0; j < 4; j++) acc[i][j] = 0.f;

    for (int k0 = 0; k0 < 512; k0 += 32) {
#pragma unroll
        for (int q = 0; q < 8; q++) {
            int i = tid + q * 256;
            int r = i >> 5, c = i & 31;
            Ps[r][c] = arow[(size_t)r * 512 + k0 + c];
        }
#pragma unroll
        for (int q = 0; q < 8; q++) {
            int i = tid + q * 256;
            int r = i >> 6, c = i & 63;
            Vs[r][c] = vbase[(size_t)(k0 + r) * 1536 + c];
        }
        __syncthreads();
#pragma unroll 8
        for (int kk = 0; kk < 32; kk++) {
            float a[4], bv[4];
#pragma unroll
            for (int i = 0; i < 4; i++) a[i] = Ps[ty * 4 + i][kk];
#pragma unroll
            for (int j = 0; j < 4; j++) bv[j] = Vs[kk][tx * 4 + j];
#pragma unroll
            for (int i = 0; i < 4; i++)
#pragma unroll
                for (int j = 0; j < 4; j++) acc[i][j] += a[i] * bv[j];
        }
        __syncthreads();
    }
#pragma unroll
    for (int i = 0; i < 4; i++)
#pragma unroll
        for (int j = 0; j < 4; j++) {
            int row = b * 512 + q0 + ty * 4 + i;
            int col = h * 64 + tx * 4 + j;
            ztan[(size_t)row * 512 + col] = acc[i][j];
        }
}

// ---------------------------------------------------------------------------
extern "C" void kernel_launch(void* const* d_in, const int* in_sizes, int n_in,
                              void* d_out, int out_size) {
    const float* x       = (const float*)d_in[0];
    const float* x_vel   = (const float*)d_in[1];
    const float* topo    = (const float*)d_in[2];
    const float* W_qkv   = (const float*)d_in[3];
    const float* W_vproj = (const float*)d_in[4];
    const float* W_proj  = (const float*)d_in[5];
    const float* b_proj  = (const float*)d_in[6];

    float* out    = (float*)d_out;
    float* z_man  = out;                                   // 32*512*513
    float* attn   = out + (size_t)BB * JJ * (EE + 1);      // 32*8*512*512
    float* x_tan  = attn + (size_t)BB * HH * JJ * JJ;      // 32*512*512

    void *pq = nullptr, *pz = nullptr, *pz2 = nullptr;
    cudaGetSymbolAddress(&pq, g_qkv);
    cudaGetSymbolAddress(&pz, g_ztan);
    cudaGetSymbolAddress(&pz2, g_ztan2);
    float* qkv   = (float*)pq;
    float* ztan  = (float*)pz;
    float* ztan2 = (float*)pz2;

    // 1. log-map -> x_tan (also an output)
    xtan_kernel<<<MROWS, 128>>>(x, x_tan);

    // 2. qkv = x_tan @ W_qkv^T   (M=16384, N=1536, K=512)
    {
        dim3 g(1536 / 128, MROWS / 128);
        gemm_nt<<<g, 256>>>(x_tan, 512, W_qkv, 512, qkv, 1536, 512, nullptr, 0);
    }
    // 3. k += v_tan @ W_vproj^T  (accumulate into k slab, cols 512..1023)
    {
        dim3 g(512 / 128, MROWS / 128);
        gemm_nt<<<g, 256>>>(x_vel + 1, 513, W_vproj, 512, qkv + 512, 1536, 512, nullptr, 1);
    }
    // 4. S = QK^T * scale + topo_bias  -> attn region (pre-softmax)
    {
        dim3 g(8, 8, BB * HH);
        s_kernel<<<g, 256>>>(qkv, topo, attn);
    }
    // 5. softmax rows in place
    softmax_kernel<<<BB * HH * JJ, 128>>>(attn);

    // 6. z_tan = attn @ V  -> (B,J,E)
    {
        dim3 g(1, 8, BB * HH);
        pv_kernel<<<g, 256>>>(attn, qkv, ztan);
    }
    // 7. out-proj: ztan2 = ztan @ W_proj^T + b_proj
    {
        dim3 g(512 / 128, MROWS / 128);
        gemm_nt<<<g, 256>>>(ztan, 512, W_proj, 512, ztan2, 512, 512, b_proj, 0);
    }
    // 8. exp-map -> z_manifold
    expmap_kernel<<<MROWS, 128>>>(ztan2, z_man);
}

// round 2
// speedup vs baseline: 2.6364x; 2.6364x over previous
#include <cuda_runtime.h>
#include <math.h>

// Problem constants
#define BB 32
#define JJ 512
#define EE 512
#define HH 8
#define MROWS (BB*JJ)          // 16384
#define EPSF 1e-7f

// Scratch (device globals; no allocation allowed)
__device__ float g_qkv[MROWS * 3 * EE];   // [16384,1536]  q|k|v per row
__device__ float g_ztan[MROWS * EE];      // attn @ v, (B,J,E)
__device__ float g_ztan2[MROWS * EE];     // after out-proj

// ---------------------------------------------------------------------------
// TF32 helpers
// ---------------------------------------------------------------------------
__device__ __forceinline__ unsigned f2tf(float x) {
    unsigned u;
    asm("cvt.rna.tf32.f32 %0, %1;" : "=r"(u) : "f"(x));
    return u;
}

__device__ __forceinline__ void mma8(float (&c)[4], const unsigned (&a)[4],
                                     const unsigned (&b)[2]) {
    asm volatile(
        "mma.sync.aligned.m16n8k8.row.col.f32.tf32.tf32.f32 "
        "{%0,%1,%2,%3},{%4,%5,%6,%7},{%8,%9},{%0,%1,%2,%3};"
        : "+f"(c[0]), "+f"(c[1]), "+f"(c[2]), "+f"(c[3])
        : "r"(a[0]), "r"(a[1]), "r"(a[2]), "r"(a[3]), "r"(b[0]), "r"(b[1]));
}

// ---------------------------------------------------------------------------
// log_map0_spatial
// ---------------------------------------------------------------------------
__global__ void xtan_kernel(const float* __restrict__ x, float* __restrict__ xt) {
    int row = blockIdx.x;
    const float* p = x + (size_t)row * 513;
    float* o = xt + (size_t)row * 512;
    int t = threadIdx.x;  // 128 threads
    float v[4];
    float s = 0.f;
#pragma unroll
    for (int q = 0; q < 4; q++) { v[q] = p[1 + t + q * 128]; s += v[q] * v[q]; }
#pragma unroll
    for (int o2 = 16; o2 > 0; o2 >>= 1) s += __shfl_xor_sync(0xffffffffu, s, o2);
    __shared__ float sb[4];
    if ((t & 31) == 0) sb[t >> 5] = s;
    __syncthreads();
    float tot = sb[0] + sb[1] + sb[2] + sb[3];
    float nrm = sqrtf(tot);
    float x0 = fmaxf(p[0], 1.0f + 1e-7f);
    float theta = acoshf(x0);
    float sc = theta / fmaxf(nrm, EPSF);
#pragma unroll
    for (int q = 0; q < 4; q++) o[t + q * 128] = sc * v[q];
}

// ---------------------------------------------------------------------------
// exp_map0
// ---------------------------------------------------------------------------
__global__ void expmap_kernel(const float* __restrict__ zt, float* __restrict__ zm) {
    int row = blockIdx.x;
    const float* p = zt + (size_t)row * 512;
    float* o = zm + (size_t)row * 513;
    int t = threadIdx.x;
    float v[4];
    float s = 0.f;
#pragma unroll
    for (int q = 0; q < 4; q++) { v[q] = p[t + q * 128]; s += v[q] * v[q]; }
#pragma unroll
    for (int o2 = 16; o2 > 0; o2 >>= 1) s += __shfl_xor_sync(0xffffffffu, s, o2);
    __shared__ float sb[4];
    if ((t & 31) == 0) sb[t >> 5] = s;
    __syncthreads();
    float tot = sb[0] + sb[1] + sb[2] + sb[3];
    float nrm = sqrtf(tot);
    float sc = sinhf(nrm) / fmaxf(nrm, EPSF);
    if (t == 0) o[0] = coshf(nrm);
#pragma unroll
    for (int q = 0; q < 4; q++) o[1 + t + q * 128] = sc * v[q];
}

// ---------------------------------------------------------------------------
// Dense TC GEMM: C[M,N] (+)= A[M,K] * W[N,K]^T (+bias), TF32 mma
// BM=BN=128, BK=16, 256 threads = 8 warps (2x4), warp tile 64x32
// ---------------------------------------------------------------------------
__global__ void __launch_bounds__(256) gemm_nt_tc(
    const float* __restrict__ A, int lda, int a_aligned,
    const float* __restrict__ W, int ldb,
    float* __restrict__ C, int ldc, int K,
    const float* __restrict__ bias, int accflag) {
    __shared__ unsigned As[128][20];
    __shared__ unsigned Bs[128][20];
    int tid = threadIdx.x, lane = tid & 31, w = tid >> 5;
    int m0w = (w >> 2) * 64, n0w = (w & 3) * 32;
    const float* Ab = A + (size_t)blockIdx.y * 128 * lda;
    const float* Wb = W + (size_t)blockIdx.x * 128 * ldb;
    float c[4][4][4];
#pragma unroll
    for (int i = 0; i < 4; i++)
#pragma unroll
        for (int j = 0; j < 4; j++)
#pragma unroll
            for (int q = 0; q < 4; q++) c[i][j][q] = 0.f;

    for (int k0 = 0; k0 < K; k0 += 16) {
        if (a_aligned) {
#pragma unroll
            for (int q = 0; q < 2; q++) {
                int i = tid + q * 256;            // 0..511
                int r = i >> 2, c4 = (i & 3) * 4;
                float4 f = *(const float4*)(Ab + (size_t)r * lda + k0 + c4);
                uint4 u = make_uint4(f2tf(f.x), f2tf(f.y), f2tf(f.z), f2tf(f.w));
                *(uint4*)&As[r][c4] = u;
            }
        } else {
#pragma unroll
            for (int q = 0; q < 8; q++) {
                int i = tid + q * 256;            // 0..2047
                int r = i >> 4, cc = i & 15;
                As[r][cc] = f2tf(Ab[(size_t)r * lda + k0 + cc]);
            }
        }
#pragma unroll
        for (int q = 0; q < 2; q++) {
            int i = tid + q * 256;
            int r = i >> 2, c4 = (i & 3) * 4;
            float4 f = *(const float4*)(Wb + (size_t)r * ldb + k0 + c4);
            uint4 u = make_uint4(f2tf(f.x), f2tf(f.y), f2tf(f.z), f2tf(f.w));
            *(uint4*)&Bs[r][c4] = u;
        }
        __syncthreads();
#pragma unroll
        for (int ks = 0; ks < 16; ks += 8) {
            unsigned af[4][4], bf[4][2];
#pragma unroll
            for (int ma = 0; ma < 4; ma++) {
                int m = m0w + ma * 16 + (lane >> 2);
                int kk = ks + (lane & 3);
                af[ma][0] = As[m][kk];
                af[ma][1] = As[m + 8][kk];
                af[ma][2] = As[m][kk + 4];
                af[ma][3] = As[m + 8][kk + 4];
            }
#pragma unroll
            for (int nb = 0; nb < 4; nb++) {
                int n = n0w + nb * 8 + (lane >> 2);
                int kk = ks + (lane & 3);
                bf[nb][0] = Bs[n][kk];
                bf[nb][1] = Bs[n][kk + 4];
            }
#pragma unroll
            for (int ma = 0; ma < 4; ma++)
#pragma unroll
                for (int nb = 0; nb < 4; nb++) mma8(c[ma][nb], af[ma], bf[nb]);
        }
        __syncthreads();
    }
    int row0 = blockIdx.y * 128 + m0w;
    int col0 = blockIdx.x * 128 + n0w;
#pragma unroll
    for (int ma = 0; ma < 4; ma++)
#pragma unroll
        for (int nb = 0; nb < 4; nb++) {
            int r = row0 + ma * 16 + (lane >> 2);
            int cc = col0 + nb * 8 + 2 * (lane & 3);
            float2 v0 = make_float2(c[ma][nb][0], c[ma][nb][1]);
            float2 v1 = make_float2(c[ma][nb][2], c[ma][nb][3]);
            if (bias) {
                float bx = bias[cc], by = bias[cc + 1];
                v0.x += bx; v0.y += by; v1.x += bx; v1.y += by;
            }
            float* p0 = &C[(size_t)r * ldc + cc];
            float* p1 = &C[(size_t)(r + 8) * ldc + cc];
            if (accflag) {
                float2 o0 = *(float2*)p0, o1 = *(float2*)p1;
                v0.x += o0.x; v0.y += o0.y; v1.x += o1.x; v1.y += o1.y;
            }
            *(float2*)p0 = v0;
            *(float2*)p1 = v1;
        }
}

// ---------------------------------------------------------------------------
// S = QK^T * scale + topo, TF32. 64x64 tile, K=64. 128 threads = 4 warps (2x2).
// grid (8, 8, 256)
// ---------------------------------------------------------------------------
__global__ void __launch_bounds__(128) s_tc(const float* __restrict__ qkv,
                                            const float* __restrict__ topo,
                                            float* __restrict__ attn) {
    int head = blockIdx.z;
    int b = head >> 3, h = head & 7;
    int k0 = blockIdx.x * 64, q0 = blockIdx.y * 64;
    __shared__ unsigned Qs[64][68];   // [m][k]
    __shared__ unsigned Ks[64][68];   // [n][k]
    int tid = threadIdx.x, lane = tid & 31, w = tid >> 5;
    int m0w = (w >> 1) * 32, n0w = (w & 1) * 32;
    const float* qbase = qkv + (size_t)b * 512 * 1536 + h * 64;
    const float* kbase = qbase + 512;
#pragma unroll
    for (int q = 0; q < 8; q++) {
        int i = tid + q * 128;          // 0..1023
        int r = i >> 4, c4 = (i & 15) * 4;
        float4 fq = *(const float4*)(qbase + (size_t)(q0 + r) * 1536 + c4);
        float4 fk = *(const float4*)(kbase + (size_t)(k0 + r) * 1536 + c4);
        *(uint4*)&Qs[r][c4] = make_uint4(f2tf(fq.x), f2tf(fq.y), f2tf(fq.z), f2tf(fq.w));
        *(uint4*)&Ks[r][c4] = make_uint4(f2tf(fk.x), f2tf(fk.y), f2tf(fk.z), f2tf(fk.w));
    }
    __syncthreads();
    float c[2][4][4];
#pragma unroll
    for (int i = 0; i < 2; i++)
#pragma unroll
        for (int j = 0; j < 4; j++)
#pragma unroll
            for (int q = 0; q < 4; q++) c[i][j][q] = 0.f;
#pragma unroll
    for (int ks = 0; ks < 64; ks += 8) {
        unsigned af[2][4], bf[4][2];
        int kk = ks + (lane & 3);
#pragma unroll
        for (int ma = 0; ma < 2; ma++) {
            int m = m0w + ma * 16 + (lane >> 2);
            af[ma][0] = Qs[m][kk];
            af[ma][1] = Qs[m + 8][kk];
            af[ma][2] = Qs[m][kk + 4];
            af[ma][3] = Qs[m + 8][kk + 4];
        }
#pragma unroll
        for (int nb = 0; nb < 4; nb++) {
            int n = n0w + nb * 8 + (lane >> 2);
            bf[nb][0] = Ks[n][kk];
            bf[nb][1] = Ks[n][kk + 4];
        }
#pragma unroll
        for (int ma = 0; ma < 2; ma++)
#pragma unroll
            for (int nb = 0; nb < 4; nb++) mma8(c[ma][nb], af[ma], bf[nb]);
    }
    const float scale = 0.125f;
#pragma unroll
    for (int ma = 0; ma < 2; ma++)
#pragma unroll
        for (int nb = 0; nb < 4; nb++) {
            int qi = q0 + m0w + ma * 16 + (lane >> 2);
            int kj = k0 + n0w + nb * 8 + 2 * (lane & 3);
            float2 t0 = *(const float2*)&topo[(size_t)qi * 512 + kj];
            float2 t1 = *(const float2*)&topo[(size_t)(qi + 8) * 512 + kj];
            float2 v0 = make_float2(c[ma][nb][0] * scale + t0.x,
                                    c[ma][nb][1] * scale + t0.y);
            float2 v1 = make_float2(c[ma][nb][2] * scale + t1.x,
                                    c[ma][nb][3] * scale + t1.y);
            *(float2*)&attn[((size_t)head * 512 + qi) * 512 + kj] = v0;
            *(float2*)&attn[((size_t)head * 512 + qi + 8) * 512 + kj] = v1;
        }
}

// ---------------------------------------------------------------------------
// Row softmax in place, one block per row (512 cols), 128 threads
// ---------------------------------------------------------------------------
__global__ void softmax_kernel(float* __restrict__ attn) {
    size_t row = blockIdx.x;
    float* p = attn + row * 512;
    int t = threadIdx.x;
    float4 v = reinterpret_cast<float4*>(p)[t];
    float m = fmaxf(fmaxf(v.x, v.y), fmaxf(v.z, v.w));
#pragma unroll
    for (int o = 16; o > 0; o >>= 1) m = fmaxf(m, __shfl_xor_sync(0xffffffffu, m, o));
    __shared__ float sb[4];
    if ((t & 31) == 0) sb[t >> 5] = m;
    __syncthreads();
    m = fmaxf(fmaxf(sb[0], sb[1]), fmaxf(sb[2], sb[3]));
    __syncthreads();
    v.x = expf(v.x - m); v.y = expf(v.y - m); v.z = expf(v.z - m); v.w = expf(v.w - m);
    float s = v.x + v.y + v.z + v.w;
#pragma unroll
    for (int o = 16; o > 0; o >>= 1) s += __shfl_xor_sync(0xffffffffu, s, o);
    if ((t & 31) == 0) sb[t >> 5] = s;
    __syncthreads();
    s = sb[0] + sb[1] + sb[2] + sb[3];
    float inv = 1.0f / s;
    v.x *= inv; v.y *= inv; v.z *= inv; v.w *= inv;
    reinterpret_cast<float4*>(p)[t] = v;
}

// ---------------------------------------------------------------------------
// z = attn @ V per head -> (B,J,E). TF32. BM=128, BN=64, BK=32.
// 256 threads = 8 warps (4x2), warp tile 32x32. grid (4, 256)
// ---------------------------------------------------------------------------
__global__ void __launch_bounds__(256) pv_tc(const float* __restrict__ attn,
                                             const float* __restrict__ qkv,
                                             float* __restrict__ ztan) {
    int head = blockIdx.y;
    int b = head >> 3, h = head & 7;
    int q0 = blockIdx.x * 128;
    __shared__ unsigned Ps[128][36];   // [m][k]
    __shared__ unsigned Vs[32][68];    // [k][n]
    int tid = threadIdx.x, lane = tid & 31, w = tid >> 5;
    int m0w = (w >> 1) * 32, n0w = (w & 1) * 32;
    const float* arow = attn + ((size_t)head * 512 + q0) * 512;
    const float* vbase = qkv + (size_t)b * 512 * 1536 + 1024 + h * 64;
    float c[2][4][4];
#pragma unroll
    for (int i = 0; i < 2; i++)
#pragma unroll
        for (int j = 0; j < 4; j++)
#pragma unroll
            for (int q = 0; q < 4; q++) c[i][j][q] = 0.f;

    for (int k0 = 0; k0 < 512; k0 += 32) {
#pragma unroll
        for (int q = 0; q < 4; q++) {
            int i = tid + q * 256;          // 0..1023 (128 rows x 8 f4)
            int r = i >> 3, c4 = (i & 7) * 4;
            float4 f = *(const float4*)(arow + (size_t)r * 512 + k0 + c4);
            *(uint4*)&Ps[r][c4] = make_uint4(f2tf(f.x), f2tf(f.y), f2tf(f.z), f2tf(f.w));
        }
#pragma unroll
        for (int q = 0; q < 2; q++) {
            int i = tid + q * 256;          // 0..511 (32 rows x 16 f4)
            int r = i >> 4, c4 = (i & 15) * 4;
            float4 f = *(const float4*)(vbase + (size_t)(k0 + r) * 1536 + c4);
            *(uint4*)&Vs[r][c4] = make_uint4(f2tf(f.x), f2tf(f.y), f2tf(f.z), f2tf(f.w));
        }
        __syncthreads();
#pragma unroll
        for (int ks = 0; ks < 32; ks += 8) {
            unsigned af[2][4], bf[4][2];
            int kk = ks + (lane & 3);
#pragma unroll
            for (int ma = 0; ma < 2; ma++) {
                int m = m0w + ma * 16 + (lane >> 2);
                af[ma][0] = Ps[m][kk];
                af[ma][1] = Ps[m + 8][kk];
                af[ma][2] = Ps[m][kk + 4];
                af[ma][3] = Ps[m + 8][kk + 4];
            }
#pragma unroll
            for (int nb = 0; nb < 4; nb++) {
                int n = n0w + nb * 8 + (lane >> 2);
                bf[nb][0] = Vs[kk][n];
                bf[nb][1] = Vs[kk + 4][n];
            }
#pragma unroll
            for (int ma = 0; ma < 2; ma++)
#pragma unroll
                for (int nb = 0; nb < 4; nb++) mma8(c[ma][nb], af[ma], bf[nb]);
        }
        __syncthreads();
    }
#pragma unroll
    for (int ma = 0; ma < 2; ma++)
#pragma unroll
        for (int nb = 0; nb < 4; nb++) {
            int row = b * 512 + q0 + m0w + ma * 16 + (lane >> 2);
            int col = h * 64 + n0w + nb * 8 + 2 * (lane & 3);
            *(float2*)&ztan[(size_t)row * 512 + col] =
                make_float2(c[ma][nb][0], c[ma][nb][1]);
            *(float2*)&ztan[(size_t)(row + 8) * 512 + col] =
                make_float2(c[ma][nb][2], c[ma][nb][3]);
        }
}

// ---------------------------------------------------------------------------
extern "C" void kernel_launch(void* const* d_in, const int* in_sizes, int n_in,
                              void* d_out, int out_size) {
    const float* x       = (const float*)d_in[0];
    const float* x_vel   = (const float*)d_in[1];
    const float* topo    = (const float*)d_in[2];
    const float* W_qkv   = (const float*)d_in[3];
    const float* W_vproj = (const float*)d_in[4];
    const float* W_proj  = (const float*)d_in[5];
    const float* b_proj  = (const float*)d_in[6];

    float* out    = (float*)d_out;
    float* z_man  = out;                                   // 32*512*513
    float* attn   = out + (size_t)BB * JJ * (EE + 1);      // 32*8*512*512
    float* x_tan  = attn + (size_t)BB * HH * JJ * JJ;      // 32*512*512

    void *pq = nullptr, *pz = nullptr, *pz2 = nullptr;
    cudaGetSymbolAddress(&pq, g_qkv);
    cudaGetSymbolAddress(&pz, g_ztan);
    cudaGetSymbolAddress(&pz2, g_ztan2);
    float* qkv   = (float*)pq;
    float* ztan  = (float*)pz;
    float* ztan2 = (float*)pz2;

    // 1. log-map -> x_tan (also an output)
    xtan_kernel<<<MROWS, 128>>>(x, x_tan);

    // 2. qkv = x_tan @ W_qkv^T   (M=16384, N=1536, K=512)
    {
        dim3 g(1536 / 128, MROWS / 128);
        gemm_nt_tc<<<g, 256>>>(x_tan, 512, 1, W_qkv, 512, qkv, 1536, 512, nullptr, 0);
    }
    // 3. k += v_tan @ W_vproj^T  (accumulate into k slab; unaligned A)
    {
        dim3 g(512 / 128, MROWS / 128);
        gemm_nt_tc<<<g, 256>>>(x_vel + 1, 513, 0, W_vproj, 512, qkv + 512, 1536, 512,
                               nullptr, 1);
    }
    // 4. S = QK^T * scale + topo_bias -> attn region (pre-softmax)
    {
        dim3 g(8, 8, BB * HH);
        s_tc<<<g, 128>>>(qkv, topo, attn);
    }
    // 5. softmax rows in place
    softmax_kernel<<<BB * HH * JJ, 128>>>(attn);

    // 6. z_tan = attn @ V -> (B,J,E)
    {
        dim3 g(4, BB * HH);
        pv_tc<<<g, 256>>>(attn, qkv, ztan);
    }
    // 7. out-proj: ztan2 = ztan @ W_proj^T + b_proj
    {
        dim3 g(512 / 128, MROWS / 128);
        gemm_nt_tc<<<g, 256>>>(ztan, 512, 1, W_proj, 512, ztan2, 512, 512, b_proj, 0);
    }
    // 8. exp-map -> z_manifold
    expmap_kernel<<<MROWS, 128>>>(ztan2, z_man);
}